// round 2
// baseline (speedup 1.0000x reference)
#include <cuda_runtime.h>
#include <cuda_bf16.h>
#include <math_constants.h>

// Problem constants
#define BB   128
#define NN   196
#define DD   768
#define NTOK (BB * NN)      // 25088
#define EPSF 1e-6f

// ---------------- static device scratch (no allocations allowed) -------------
__device__ float    g_sim[(size_t)BB * NN * NN];   // ~19.7 MB
__device__ float    g_rnorm[NTOK];
__device__ float    g_imp[NTOK];
__device__ float    g_w[NTOK];
__device__ int      g_gids[NTOK];
__device__ int      g_members[NTOK];
__device__ int      g_goff[BB * (NN + 1)];
__device__ float    g_gmax[2];

// ---------------- kernel 1: global max of motion / saliency ------------------
__global__ void gmax_kernel(const float* __restrict__ m,
                            const float* __restrict__ s, int n) {
    const float* p = (blockIdx.x == 0) ? m : s;
    float mx = -CUDART_INF_F;
    for (int i = threadIdx.x; i < n; i += blockDim.x) mx = fmaxf(mx, p[i]);
    __shared__ float sh[256];
    sh[threadIdx.x] = mx;
    __syncthreads();
    for (int o = 128; o; o >>= 1) {
        if (threadIdx.x < o) sh[threadIdx.x] = fmaxf(sh[threadIdx.x], sh[threadIdx.x + o]);
        __syncthreads();
    }
    if (threadIdx.x == 0) g_gmax[blockIdx.x] = sh[0];
}

// ---------------- kernel 2: importance per batch -----------------------------
__global__ void imp_kernel(const float* __restrict__ m,
                           const float* __restrict__ s,
                           float* out_imp) {
    int b = blockIdx.x, t = threadIdx.x;
    __shared__ float lo[256], hi[256];
    bool valid = (t < NN);
    float v = 0.f;
    if (valid) {
        float mn = m[b * NN + t] / (g_gmax[0] + EPSF);
        float sn = s[b * NN + t] / (g_gmax[1] + EPSF);
        v = 0.5f * mn + 0.5f * sn;   // (1 - 0.5 - 0.5) * ratio == 0 exactly
    }
    lo[t] = valid ? v :  CUDART_INF_F;
    hi[t] = valid ? v : -CUDART_INF_F;
    __syncthreads();
    for (int o = 128; o; o >>= 1) {
        if (t < o) { lo[t] = fminf(lo[t], lo[t + o]); hi[t] = fmaxf(hi[t], hi[t + o]); }
        __syncthreads();
    }
    float l = lo[0], h = hi[0];
    if (valid) {
        float r = (v - l) / (h - l + EPSF);
        g_imp[b * NN + t] = r;
        if (out_imp) out_imp[b * NN + t] = r;
    }
}

// ---------------- kernel 3: reciprocal token norms ----------------------------
__global__ void rnorm_kernel(const float* __restrict__ tok) {
    int warp = (blockIdx.x * blockDim.x + threadIdx.x) >> 5;
    int lane = threadIdx.x & 31;
    if (warp >= NTOK) return;
    const float* tr = tok + (size_t)warp * DD;
    float acc = 0.f;
    for (int k = lane; k < DD; k += 32) { float v = tr[k]; acc += v * v; }
    #pragma unroll
    for (int o = 16; o; o >>= 1) acc += __shfl_xor_sync(0xffffffffu, acc, o);
    if (lane == 0) {
        float nrm = fmaxf(sqrtf(acc), 1e-12f);
        g_rnorm[warp] = 1.0f / nrm;
    }
}

// ---------------- kernel 4: cosine similarity GEMM (symmetric) ----------------
// 64x64 tile, BK=16, 4x4 per thread, 256 threads. Computes tile pairs ti<=tj,
// writes both the tile and its transpose. Normalization folded in at load.
#define BM 64
#define BK 16
__global__ void __launch_bounds__(256, 4)
sim_kernel(const float* __restrict__ tok, float* __restrict__ out_sim) {
    __shared__ float As[BK][BM + 4];
    __shared__ float Bs[BK][BM + 4];
    __shared__ float rnA[BM], rnB[BM];

    const int ti_tab[10] = {0,0,0,0,1,1,1,2,2,3};
    const int tj_tab[10] = {0,1,2,3,1,2,3,2,3,3};
    int b  = blockIdx.z;
    int i0 = ti_tab[blockIdx.x] * BM;
    int j0 = tj_tab[blockIdx.x] * BM;
    int tid = threadIdx.x;

    if (tid < BM)            rnA[tid]      = (i0 + tid      < NN) ? g_rnorm[b * NN + i0 + tid]      : 0.f;
    else if (tid < 2 * BM) { int r = tid - BM;
                             rnB[r]        = (j0 + r        < NN) ? g_rnorm[b * NN + j0 + r]        : 0.f; }
    __syncthreads();

    int row = tid >> 2, c4 = tid & 3;
    int tx  = tid & 15, ty = tid >> 4;
    float acc[4][4];
    #pragma unroll
    for (int m = 0; m < 4; m++)
        #pragma unroll
        for (int n = 0; n < 4; n++) acc[m][n] = 0.f;

    const float* tokb = tok + (size_t)b * NN * DD;

    for (int kt = 0; kt < DD; kt += BK) {
        int k = kt + c4 * 4;
        float4 va = make_float4(0.f, 0.f, 0.f, 0.f);
        float4 vb = make_float4(0.f, 0.f, 0.f, 0.f);
        if (i0 + row < NN) va = *(const float4*)(tokb + (size_t)(i0 + row) * DD + k);
        if (j0 + row < NN) vb = *(const float4*)(tokb + (size_t)(j0 + row) * DD + k);
        float ra = rnA[row], rb = rnB[row];
        As[c4 * 4 + 0][row] = va.x * ra; As[c4 * 4 + 1][row] = va.y * ra;
        As[c4 * 4 + 2][row] = va.z * ra; As[c4 * 4 + 3][row] = va.w * ra;
        Bs[c4 * 4 + 0][row] = vb.x * rb; Bs[c4 * 4 + 1][row] = vb.y * rb;
        Bs[c4 * 4 + 2][row] = vb.z * rb; Bs[c4 * 4 + 3][row] = vb.w * rb;
        __syncthreads();
        #pragma unroll
        for (int kk = 0; kk < BK; kk++) {
            float4 a4 = *(const float4*)&As[kk][ty * 4];
            float4 b4 = *(const float4*)&Bs[kk][tx * 4];
            float a[4] = {a4.x, a4.y, a4.z, a4.w};
            float c[4] = {b4.x, b4.y, b4.z, b4.w};
            #pragma unroll
            for (int m = 0; m < 4; m++)
                #pragma unroll
                for (int n = 0; n < 4; n++)
                    acc[m][n] += a[m] * c[n];
        }
        __syncthreads();
    }

    #pragma unroll
    for (int m = 0; m < 4; m++) {
        int gi = i0 + ty * 4 + m;
        if (gi >= NN) continue;
        #pragma unroll
        for (int n = 0; n < 4; n++) {
            int gj = j0 + tx * 4 + n;
            if (gj >= NN) continue;
            float v = acc[m][n];
            if (gi == gj) v = 0.f;
            size_t o1 = ((size_t)b * NN + gi) * NN + gj;
            size_t o2 = ((size_t)b * NN + gj) * NN + gi;
            g_sim[o1] = v;
            g_sim[o2] = v;
            if (out_sim) { out_sim[o1] = v; out_sim[o2] = v; }
        }
    }
}

// ---------------- kernel 5: sequential BFS grouping + weights + CSR -----------
__global__ void __launch_bounds__(256, 1)
group_kernel(float* out_gids) {
    int b = blockIdx.x, tid = threadIdx.x;
    __shared__ unsigned adj[NN][8];
    __shared__ float simp[NN];
    __shared__ int   sgid[NN];
    __shared__ float denom[NN];
    __shared__ int   cnt[NN];
    __shared__ int   off[NN + 1];
    __shared__ int   cur[NN];
    __shared__ unsigned assigned[8], reach[8], nxt[8];
    __shared__ int s_changed, s_ng;

    for (int i = tid; i < NN * 8; i += 256) (&adj[0][0])[i] = 0u;
    for (int i = tid; i < NN; i += 256) {
        simp[i] = g_imp[b * NN + i];
        cnt[i] = 0;
        denom[i] = EPSF;
    }
    if (tid < 8) assigned[tid] = 0u;
    if (tid == 0) s_ng = 0;
    __syncthreads();

    // build directed adjacency bitmask: adj[i] has bit j iff sim>0.9 && (1-imp_i)>0.5
    const float* simb = g_sim + (size_t)b * NN * NN;
    for (int idx = tid; idx < NN * NN; idx += 256) {
        int i = idx / NN, j = idx - i * NN;
        float sv = simb[idx];
        if (sv > 0.9f && (1.0f - simp[i]) > 0.5f)
            atomicOr(&adj[i][j >> 5], 1u << (j & 31));
    }
    __syncthreads();

    // sequential roots, BFS fixpoint through unassigned nodes
    for (int r = 0; r < NN; r++) {
        if ((assigned[r >> 5] >> (r & 31)) & 1u) continue;   // uniform
        if (tid < 8) reach[tid] = (tid == (r >> 5)) ? (1u << (r & 31)) : 0u;
        __syncthreads();
        while (true) {
            if (tid < 8) nxt[tid] = 0u;
            if (tid == 0) s_changed = 0;
            __syncthreads();
            for (int i = tid; i < NN; i += 256) {
                if ((reach[i >> 5] >> (i & 31)) & 1u) {
                    #pragma unroll
                    for (int w = 0; w < 7; w++) {
                        unsigned v = adj[i][w];
                        if (v) atomicOr(&nxt[w], v);
                    }
                }
            }
            __syncthreads();
            if (tid < 8) {
                unsigned nv = reach[tid] | (nxt[tid] & ~assigned[tid]);
                if (nv != reach[tid]) s_changed = 1;
                nxt[tid] = nv;
            }
            __syncthreads();
            if (tid < 8) reach[tid] = nxt[tid];
            __syncthreads();
            if (!s_changed) break;
        }
        int gid = s_ng;
        for (int i = tid; i < NN; i += 256)
            if ((reach[i >> 5] >> (i & 31)) & 1u) sgid[i] = gid;
        if (tid < 8) assigned[tid] |= reach[tid];
        __syncthreads();
        if (tid == 0) s_ng = gid + 1;
        __syncthreads();
    }

    // per-group importance sums -> weights
    for (int i = tid; i < NN; i += 256) atomicAdd(&denom[sgid[i]], simp[i]);
    __syncthreads();
    for (int i = tid; i < NN; i += 256) {
        g_w[b * NN + i]    = simp[i] / denom[sgid[i]];
        g_gids[b * NN + i] = sgid[i];
        if (out_gids) out_gids[b * NN + i] = (float)sgid[i];
        atomicAdd(&cnt[sgid[i]], 1);
    }
    __syncthreads();
    if (tid == 0) {
        off[0] = 0;
        for (int g = 0; g < NN; g++) off[g + 1] = off[g] + cnt[g];
    }
    __syncthreads();
    for (int g = tid; g < NN; g += 256) cur[g] = off[g];
    for (int g = tid; g < NN + 1; g += 256) g_goff[b * (NN + 1) + g] = off[g];
    __syncthreads();
    for (int i = tid; i < NN; i += 256) {
        int g = sgid[i];
        int pos = atomicAdd(&cur[g], 1);
        g_members[b * NN + pos] = i;
    }
}

// ---------------- kernel 6: merged tokens (CSR gather, atomic-free) -----------
__global__ void __launch_bounds__(256)
merge_kernel(const float* __restrict__ tok, float* __restrict__ out) {
    int b = blockIdx.y, g = blockIdx.x, tid = threadIdx.x;
    int o0 = g_goff[b * (NN + 1) + g];
    int o1 = g_goff[b * (NN + 1) + g + 1];
    float a0 = 0.f, a1 = 0.f, a2 = 0.f;
    const float* tokb = tok + (size_t)b * NN * DD;
    for (int k = o0; k < o1; k++) {
        int i = g_members[b * NN + k];
        float wv = g_w[b * NN + i];
        const float* tr = tokb + (size_t)i * DD;
        a0 += tr[tid] * wv;
        a1 += tr[tid + 256] * wv;
        a2 += tr[tid + 512] * wv;
    }
    float* orow = out + ((size_t)b * NN + g) * DD;
    orow[tid]       = a0;
    orow[tid + 256] = a1;
    orow[tid + 512] = a2;
}

// ---------------- launch ------------------------------------------------------
extern "C" void kernel_launch(void* const* d_in, const int* in_sizes, int n_in,
                              void* d_out, int out_size) {
    const float* tokens = (const float*)d_in[0];
    const float* motion = (const float*)d_in[1];
    const float* sal    = (const float*)d_in[2];
    // d_in[3] = compression_ratio: coefficient is exactly 0, unused.
    float* out = (float*)d_out;

    const long long SZ_M = (long long)BB * NN * DD;   // 19267584
    const long long SZ_S = (long long)BB * NN * NN;   //  4917248
    const long long SZ_I = (long long)BB * NN;        //    25088
    long long osz = (long long)out_size;

    float* out_sim  = (osz >= SZ_M + SZ_S)               ? out + SZ_M               : nullptr;
    float* out_imp  = (osz >= SZ_M + SZ_S + SZ_I)        ? out + SZ_M + SZ_S        : nullptr;
    float* out_gids = (osz >= SZ_M + SZ_S + 2 * SZ_I)    ? out + SZ_M + SZ_S + SZ_I : nullptr;

    gmax_kernel<<<2, 256>>>(motion, sal, NTOK);
    imp_kernel<<<BB, 256>>>(motion, sal, out_imp);
    rnorm_kernel<<<(NTOK * 32 + 255) / 256, 256>>>(tokens);
    sim_kernel<<<dim3(10, 1, BB), 256>>>(tokens, out_sim);
    group_kernel<<<BB, 256>>>(out_gids);
    merge_kernel<<<dim3(NN, BB), 256>>>(tokens, out);
}

// round 4
// speedup vs baseline: 2.5764x; 2.5764x over previous
#include <cuda_runtime.h>
#include <cuda_bf16.h>
#include <math_constants.h>

// Problem constants
#define BB   128
#define NN   196
#define DD   768
#define NTOK (BB * NN)      // 25088
#define EPSF 1e-6f

// ---------------- static device scratch (no allocations allowed) -------------
__device__ float    g_sim[(size_t)BB * NN * NN];   // ~19.7 MB
__device__ float    g_rnorm[NTOK];
__device__ float    g_imp[NTOK];
__device__ float    g_w[NTOK];
__device__ int      g_gids[NTOK];
__device__ int      g_members[NTOK];
__device__ int      g_goff[BB * (NN + 1)];
__device__ unsigned g_gmax_u[2];

// ---------------- kernel 0: init global-max slots -----------------------------
__global__ void gmax_init_kernel() {
    if (threadIdx.x < 2) g_gmax_u[threadIdx.x] = 0u;
}

// ---------------- kernel 1: global max of motion / saliency (atomicMax) -------
// Values are uniform in [0,1) => non-negative => float bit pattern is monotonic.
__global__ void gmax_kernel(const float* __restrict__ m,
                            const float* __restrict__ s, int n) {
    const float* p = (blockIdx.y == 0) ? m : s;
    float mx = 0.f;
    for (int i = blockIdx.x * blockDim.x + threadIdx.x; i < n; i += gridDim.x * blockDim.x)
        mx = fmaxf(mx, p[i]);
    #pragma unroll
    for (int o = 16; o; o >>= 1) mx = fmaxf(mx, __shfl_xor_sync(0xffffffffu, mx, o));
    __shared__ float sh[8];
    int lane = threadIdx.x & 31, warp = threadIdx.x >> 5;
    if (lane == 0) sh[warp] = mx;
    __syncthreads();
    if (threadIdx.x == 0) {
        float v = sh[0];
        for (int w = 1; w < (int)(blockDim.x >> 5); w++) v = fmaxf(v, sh[w]);
        atomicMax(&g_gmax_u[blockIdx.y], __float_as_uint(v));
    }
}

// ---------------- kernel 2: importance per batch -----------------------------
__global__ void imp_kernel(const float* __restrict__ m,
                           const float* __restrict__ s,
                           float* out_imp) {
    int b = blockIdx.x, t = threadIdx.x;
    __shared__ float lo[256], hi[256];
    bool valid = (t < NN);
    float v = 0.f;
    if (valid) {
        float gm0 = __uint_as_float(g_gmax_u[0]);
        float gm1 = __uint_as_float(g_gmax_u[1]);
        float mn = m[b * NN + t] / (gm0 + EPSF);
        float sn = s[b * NN + t] / (gm1 + EPSF);
        v = 0.5f * mn + 0.5f * sn;   // (1 - 0.5 - 0.5) * ratio == 0 exactly
    }
    lo[t] = valid ? v :  CUDART_INF_F;
    hi[t] = valid ? v : -CUDART_INF_F;
    __syncthreads();
    for (int o = 128; o; o >>= 1) {
        if (t < o) { lo[t] = fminf(lo[t], lo[t + o]); hi[t] = fmaxf(hi[t], hi[t + o]); }
        __syncthreads();
    }
    float l = lo[0], h = hi[0];
    if (valid) {
        float r = (v - l) / (h - l + EPSF);
        g_imp[b * NN + t] = r;
        if (out_imp) out_imp[b * NN + t] = r;
    }
}

// ---------------- kernel 3: reciprocal token norms (float4) -------------------
__global__ void rnorm_kernel(const float* __restrict__ tok) {
    int warp = (blockIdx.x * blockDim.x + threadIdx.x) >> 5;
    int lane = threadIdx.x & 31;
    if (warp >= NTOK) return;
    const float4* tr = (const float4*)(tok + (size_t)warp * DD);
    float acc = 0.f;
    #pragma unroll
    for (int it = 0; it < 6; it++) {
        float4 v = tr[lane + it * 32];
        acc += v.x * v.x + v.y * v.y + v.z * v.z + v.w * v.w;
    }
    #pragma unroll
    for (int o = 16; o; o >>= 1) acc += __shfl_xor_sync(0xffffffffu, acc, o);
    if (lane == 0) {
        float nrm = fmaxf(sqrtf(acc), 1e-12f);
        g_rnorm[warp] = 1.0f / nrm;
    }
}

// ---------------- kernel 4: cosine similarity via tf32 tensor cores ----------
// CTA tile 128x128, 8 warps (2x4), warp tile 64x32, mma.m16n8k8.tf32.
// Symmetric tile pairs: (0,0), (0,128), (128,128); mirror stores.
#define TK 32
#define AS_STRIDE 36   // +4 pad: conflict-free frag loads, 144B row = 16B aligned

__device__ __forceinline__ float to_tf32(float x) {
    float r; asm("cvt.rna.tf32.f32 %0, %1;" : "=f"(r) : "f"(x)); return r;
}
__device__ __forceinline__ void mma_tf32(float (&d)[4], const unsigned (&a)[4],
                                         const unsigned (&b)[2]) {
    asm volatile("mma.sync.aligned.m16n8k8.row.col.f32.tf32.tf32.f32 "
                 "{%0,%1,%2,%3}, {%4,%5,%6,%7}, {%8,%9}, {%0,%1,%2,%3};\n"
                 : "+f"(d[0]), "+f"(d[1]), "+f"(d[2]), "+f"(d[3])
                 : "r"(a[0]), "r"(a[1]), "r"(a[2]), "r"(a[3]),
                   "r"(b[0]), "r"(b[1]));
}

__global__ void __launch_bounds__(256, 2)
sim_kernel(const float* __restrict__ tok, float* __restrict__ out_sim) {
    __shared__ float As[128][AS_STRIDE];
    __shared__ float Bs[128][AS_STRIDE];
    __shared__ float rnA[128], rnB[128];

    int b  = blockIdx.z;
    int i0 = (blockIdx.x == 2) ? 128 : 0;
    int j0 = (blockIdx.x >= 1) ? 128 : 0;
    int tid  = threadIdx.x;
    int lane = tid & 31, warp = tid >> 5;
    int wm = warp >> 2, wn = warp & 3;
    int g4 = lane >> 2, t4 = lane & 3;

    if (tid < 128)       rnA[tid]       = (i0 + tid < NN)       ? g_rnorm[b * NN + i0 + tid]       : 0.f;
    else { int r = tid - 128;
                         rnB[r]         = (j0 + r   < NN)       ? g_rnorm[b * NN + j0 + r]         : 0.f; }

    float acc[4][4][4];   // [m-atom][n-atom][4]
    #pragma unroll
    for (int ma = 0; ma < 4; ma++)
        #pragma unroll
        for (int na = 0; na < 4; na++)
            #pragma unroll
            for (int q = 0; q < 4; q++) acc[ma][na][q] = 0.f;

    const float* tokb = tok + (size_t)b * NN * DD;
    __syncthreads();

    for (int kt = 0; kt < DD; kt += TK) {
        // fill As/Bs: 128 rows x 32 cols, tf32-rounded, rnorm folded in
        #pragma unroll
        for (int it = 0; it < 4; it++) {
            int idx = tid + it * 256;          // 0..1023
            int row = idx >> 3;                // 0..127
            int kf  = (idx & 7) * 4;           // 0..28
            float4 va = make_float4(0.f, 0.f, 0.f, 0.f);
            float4 vb = make_float4(0.f, 0.f, 0.f, 0.f);
            if (i0 + row < NN) va = *(const float4*)(tokb + (size_t)(i0 + row) * DD + kt + kf);
            if (j0 + row < NN) vb = *(const float4*)(tokb + (size_t)(j0 + row) * DD + kt + kf);
            float ra = rnA[row], rb = rnB[row];
            *(float4*)&As[row][kf] = make_float4(to_tf32(va.x * ra), to_tf32(va.y * ra),
                                                 to_tf32(va.z * ra), to_tf32(va.w * ra));
            *(float4*)&Bs[row][kf] = make_float4(to_tf32(vb.x * rb), to_tf32(vb.y * rb),
                                                 to_tf32(vb.z * rb), to_tf32(vb.w * rb));
        }
        __syncthreads();

        #pragma unroll
        for (int ks = 0; ks < 4; ks++) {
            int kb = ks * 8 + t4;
            unsigned afr[4][4];
            #pragma unroll
            for (int ma = 0; ma < 4; ma++) {
                int r = wm * 64 + ma * 16 + g4;
                afr[ma][0] = __float_as_uint(As[r    ][kb    ]);
                afr[ma][1] = __float_as_uint(As[r + 8][kb    ]);
                afr[ma][2] = __float_as_uint(As[r    ][kb + 4]);
                afr[ma][3] = __float_as_uint(As[r + 8][kb + 4]);
            }
            unsigned bfr[4][2];
            #pragma unroll
            for (int na = 0; na < 4; na++) {
                int c = wn * 32 + na * 8 + g4;
                bfr[na][0] = __float_as_uint(Bs[c][kb    ]);
                bfr[na][1] = __float_as_uint(Bs[c][kb + 4]);
            }
            #pragma unroll
            for (int ma = 0; ma < 4; ma++)
                #pragma unroll
                for (int na = 0; na < 4; na++)
                    mma_tf32(acc[ma][na], afr[ma], bfr[na]);
        }
        __syncthreads();
    }

    // epilogue: zero diagonal, store tile + mirror
    #pragma unroll
    for (int ma = 0; ma < 4; ma++) {
        #pragma unroll
        for (int na = 0; na < 4; na++) {
            int gi0 = i0 + wm * 64 + ma * 16 + g4;
            int gj0 = j0 + wn * 32 + na * 8 + 2 * t4;
            #pragma unroll
            for (int h = 0; h < 2; h++) {     // h=0 -> c0,c1 ; h=1 -> c2,c3
                int gi = gi0 + h * 8;
                if (gi >= NN || gj0 >= NN) continue;
                float v0 = acc[ma][na][h * 2 + 0];
                float v1 = acc[ma][na][h * 2 + 1];
                if (gi == gj0)     v0 = 0.f;
                if (gi == gj0 + 1) v1 = 0.f;
                size_t o1 = ((size_t)b * NN + gi) * NN + gj0;
                *(float2*)&g_sim[o1] = make_float2(v0, v1);
                size_t m0 = ((size_t)b * NN + gj0) * NN + gi;
                size_t m1 = ((size_t)b * NN + gj0 + 1) * NN + gi;
                g_sim[m0] = v0;
                g_sim[m1] = v1;
                if (out_sim) {
                    *(float2*)&out_sim[o1] = make_float2(v0, v1);
                    out_sim[m0] = v0;
                    out_sim[m1] = v1;
                }
            }
        }
    }
}

// ---------------- kernel 5: grouping (fast path for empty adjacency) ---------
__global__ void __launch_bounds__(256, 1)
group_kernel(float* out_gids) {
    int b = blockIdx.x, tid = threadIdx.x;
    __shared__ unsigned adj[NN][8];
    __shared__ float simp[NN];
    __shared__ int   sgid[NN];
    __shared__ float denom[NN];
    __shared__ int   cnt[NN];
    __shared__ int   off[NN + 1];
    __shared__ int   cur[NN];
    __shared__ unsigned assigned[8], reach[8], nxt[8];
    __shared__ int s_changed, s_ng, s_any;

    for (int i = tid; i < NN * 8; i += 256) (&adj[0][0])[i] = 0u;
    for (int i = tid; i < NN; i += 256) {
        simp[i] = g_imp[b * NN + i];
        cnt[i] = 0;
        denom[i] = EPSF;
    }
    if (tid < 8) assigned[tid] = 0u;
    if (tid == 0) { s_ng = 0; s_any = 0; }
    __syncthreads();

    // directed adjacency: adj[i] bit j iff sim>0.9 && (1-imp_i)>0.5
    const float* simb = g_sim + (size_t)b * NN * NN;
    for (int idx = tid; idx < NN * NN; idx += 256) {
        int i = idx / NN, j = idx - i * NN;
        float sv = simb[idx];
        if (sv > 0.9f && (1.0f - simp[i]) > 0.5f) {
            atomicOr(&adj[i][j >> 5], 1u << (j & 31));
            s_any = 1;
        }
    }
    __syncthreads();

    if (s_any == 0) {
        // no edges: every token is its own group, in root order
        for (int i = tid; i < NN; i += 256) sgid[i] = i;
        if (tid == 0) s_ng = NN;
        __syncthreads();
    } else {
        // sequential roots, BFS fixpoint through unassigned nodes
        for (int r = 0; r < NN; r++) {
            if ((assigned[r >> 5] >> (r & 31)) & 1u) continue;   // uniform
            if (tid < 8) reach[tid] = (tid == (r >> 5)) ? (1u << (r & 31)) : 0u;
            __syncthreads();
            while (true) {
                if (tid < 8) nxt[tid] = 0u;
                if (tid == 0) s_changed = 0;
                __syncthreads();
                for (int i = tid; i < NN; i += 256) {
                    if ((reach[i >> 5] >> (i & 31)) & 1u) {
                        #pragma unroll
                        for (int w = 0; w < 7; w++) {
                            unsigned v = adj[i][w];
                            if (v) atomicOr(&nxt[w], v);
                        }
                    }
                }
                __syncthreads();
                if (tid < 8) {
                    unsigned nv = reach[tid] | (nxt[tid] & ~assigned[tid]);
                    if (nv != reach[tid]) s_changed = 1;
                    nxt[tid] = nv;
                }
                __syncthreads();
                if (tid < 8) reach[tid] = nxt[tid];
                __syncthreads();
                if (!s_changed) break;
            }
            int gid = s_ng;
            for (int i = tid; i < NN; i += 256)
                if ((reach[i >> 5] >> (i & 31)) & 1u) sgid[i] = gid;
            if (tid < 8) assigned[tid] |= reach[tid];
            __syncthreads();
            if (tid == 0) s_ng = gid + 1;
            __syncthreads();
        }
    }

    // per-group importance sums -> weights
    for (int i = tid; i < NN; i += 256) atomicAdd(&denom[sgid[i]], simp[i]);
    __syncthreads();
    for (int i = tid; i < NN; i += 256) {
        g_w[b * NN + i]    = simp[i] / denom[sgid[i]];
        g_gids[b * NN + i] = sgid[i];
        if (out_gids) out_gids[b * NN + i] = (float)sgid[i];
        atomicAdd(&cnt[sgid[i]], 1);
    }
    __syncthreads();
    if (tid == 0) {
        off[0] = 0;
        for (int g = 0; g < NN; g++) off[g + 1] = off[g] + cnt[g];
    }
    __syncthreads();
    for (int g = tid; g < NN; g += 256) cur[g] = off[g];
    for (int g = tid; g < NN + 1; g += 256) g_goff[b * (NN + 1) + g] = off[g];
    __syncthreads();
    for (int i = tid; i < NN; i += 256) {
        int g = sgid[i];
        int pos = atomicAdd(&cur[g], 1);
        g_members[b * NN + pos] = i;
    }
}

// ---------------- kernel 6: merged tokens (CSR gather, float4) ----------------
__global__ void __launch_bounds__(192)
merge_kernel(const float* __restrict__ tok, float* __restrict__ out) {
    int b = blockIdx.y, g = blockIdx.x, tid = threadIdx.x;
    int o0 = g_goff[b * (NN + 1) + g];
    int o1 = g_goff[b * (NN + 1) + g + 1];
    float4 a = make_float4(0.f, 0.f, 0.f, 0.f);
    const float4* tokb = (const float4*)(tok + (size_t)b * NN * DD);
    for (int k = o0; k < o1; k++) {
        int i = g_members[b * NN + k];
        float wv = g_w[b * NN + i];
        float4 v = tokb[(size_t)i * (DD / 4) + tid];
        a.x += v.x * wv; a.y += v.y * wv; a.z += v.z * wv; a.w += v.w * wv;
    }
    ((float4*)out)[((size_t)b * NN + g) * (DD / 4) + tid] = a;
}

// ---------------- launch ------------------------------------------------------
extern "C" void kernel_launch(void* const* d_in, const int* in_sizes, int n_in,
                              void* d_out, int out_size) {
    const float* tokens = (const float*)d_in[0];
    const float* motion = (const float*)d_in[1];
    const float* sal    = (const float*)d_in[2];
    // d_in[3] = compression_ratio: coefficient is exactly 0, unused.
    float* out = (float*)d_out;

    const long long SZ_M = (long long)BB * NN * DD;   // 19267584
    const long long SZ_S = (long long)BB * NN * NN;   //  4917248
    const long long SZ_I = (long long)BB * NN;        //    25088
    long long osz = (long long)out_size;

    float* out_sim  = (osz >= SZ_M + SZ_S)               ? out + SZ_M               : nullptr;
    float* out_imp  = (osz >= SZ_M + SZ_S + SZ_I)        ? out + SZ_M + SZ_S        : nullptr;
    float* out_gids = (osz >= SZ_M + SZ_S + 2 * SZ_I)    ? out + SZ_M + SZ_S + SZ_I : nullptr;

    gmax_init_kernel<<<1, 32>>>();
    gmax_kernel<<<dim3(16, 2), 256>>>(motion, sal, NTOK);
    imp_kernel<<<BB, 256>>>(motion, sal, out_imp);
    rnorm_kernel<<<(NTOK * 32 + 255) / 256, 256>>>(tokens);
    sim_kernel<<<dim3(3, 1, BB), 256>>>(tokens, out_sim);
    group_kernel<<<BB, 256>>>(out_gids);
    merge_kernel<<<dim3(NN, BB), 192>>>(tokens, out);
}

// round 7
// speedup vs baseline: 2.7834x; 1.0803x over previous
#include <cuda_runtime.h>
#include <cuda_bf16.h>
#include <math_constants.h>
#include <cstdint>

// Problem constants
#define BB   128
#define NN   196
#define DD   768
#define NTOK (BB * NN)      // 25088
#define EPSF 1e-6f

// ---------------- static device scratch (no allocations allowed) -------------
__device__ float    g_sim[(size_t)BB * NN * NN];   // fallback only (~19.7 MB)
__device__ float    g_rnorm[NTOK];
__device__ float    g_imp[NTOK];
__device__ float    g_w[NTOK];
__device__ int      g_gids[NTOK];
__device__ int      g_members[NTOK];
__device__ int      g_goff[BB * (NN + 1)];
__device__ unsigned g_gmax_u[2];

// ---------------- kernel 0/1: global max of motion / saliency -----------------
__global__ void gmax_init_kernel() {
    if (threadIdx.x < 2) g_gmax_u[threadIdx.x] = 0u;
}
__global__ void gmax_kernel(const float* __restrict__ m,
                            const float* __restrict__ s, int n) {
    const float* p = (blockIdx.y == 0) ? m : s;
    float mx = 0.f;
    for (int i = blockIdx.x * blockDim.x + threadIdx.x; i < n; i += gridDim.x * blockDim.x)
        mx = fmaxf(mx, p[i]);
    #pragma unroll
    for (int o = 16; o; o >>= 1) mx = fmaxf(mx, __shfl_xor_sync(0xffffffffu, mx, o));
    __shared__ float sh[8];
    int lane = threadIdx.x & 31, warp = threadIdx.x >> 5;
    if (lane == 0) sh[warp] = mx;
    __syncthreads();
    if (threadIdx.x == 0) {
        float v = sh[0];
        for (int w = 1; w < (int)(blockDim.x >> 5); w++) v = fmaxf(v, sh[w]);
        atomicMax(&g_gmax_u[blockIdx.y], __float_as_uint(v));
    }
}

// ---------------- kernel 2: importance per batch -----------------------------
__global__ void imp_kernel(const float* __restrict__ m,
                           const float* __restrict__ s,
                           float* out_imp) {
    int b = blockIdx.x, t = threadIdx.x;
    __shared__ float lo[256], hi[256];
    bool valid = (t < NN);
    float v = 0.f;
    if (valid) {
        float gm0 = __uint_as_float(g_gmax_u[0]);
        float gm1 = __uint_as_float(g_gmax_u[1]);
        float mn = m[b * NN + t] / (gm0 + EPSF);
        float sn = s[b * NN + t] / (gm1 + EPSF);
        v = 0.5f * mn + 0.5f * sn;
    }
    lo[t] = valid ? v :  CUDART_INF_F;
    hi[t] = valid ? v : -CUDART_INF_F;
    __syncthreads();
    for (int o = 128; o; o >>= 1) {
        if (t < o) { lo[t] = fminf(lo[t], lo[t + o]); hi[t] = fmaxf(hi[t], hi[t + o]); }
        __syncthreads();
    }
    float l = lo[0], h = hi[0];
    if (valid) {
        float r = (v - l) / (h - l + EPSF);
        g_imp[b * NN + t] = r;
        if (out_imp) out_imp[b * NN + t] = r;
    }
}

// ---------------- kernel 3: reciprocal token norms (float4) -------------------
__global__ void rnorm_kernel(const float* __restrict__ tok) {
    int warp = (blockIdx.x * blockDim.x + threadIdx.x) >> 5;
    int lane = threadIdx.x & 31;
    if (warp >= NTOK) return;
    const float4* tr = (const float4*)(tok + (size_t)warp * DD);
    float acc = 0.f;
    #pragma unroll
    for (int it = 0; it < 6; it++) {
        float4 v = tr[lane + it * 32];
        acc += v.x * v.x + v.y * v.y + v.z * v.z + v.w * v.w;
    }
    #pragma unroll
    for (int o = 16; o; o >>= 1) acc += __shfl_xor_sync(0xffffffffu, acc, o);
    if (lane == 0) {
        float nrm = fmaxf(sqrtf(acc), 1e-12f);
        g_rnorm[warp] = 1.0f / nrm;
    }
}

// ---------------- kernel 4: cosine similarity via tf32 mma.sync (pipelined) ---
// CTA = one 128x128 quadrant of one batch's sim matrix (grid 4 x BB).
// 8 warps (2x4), warp tile 64x32, mma.m16n8k8.tf32. K-chunk 16, register
// prefetch + double-buffered smem, one __syncthreads per chunk.
#define KC   16
#define NCH  (DD / KC)     // 48
#define SSTR 20            // smem row stride (floats): conflict-free frag LDS

__device__ __forceinline__ float to_tf32(float x) {
    float r; asm("cvt.rna.tf32.f32 %0, %1;" : "=f"(r) : "f"(x)); return r;
}
__device__ __forceinline__ void mma_tf32(float (&d)[4], const unsigned (&a)[4],
                                         const unsigned (&b)[2]) {
    asm volatile("mma.sync.aligned.m16n8k8.row.col.f32.tf32.tf32.f32 "
                 "{%0,%1,%2,%3}, {%4,%5,%6,%7}, {%8,%9}, {%0,%1,%2,%3};\n"
                 : "+f"(d[0]), "+f"(d[1]), "+f"(d[2]), "+f"(d[3])
                 : "r"(a[0]), "r"(a[1]), "r"(a[2]), "r"(a[3]),
                   "r"(b[0]), "r"(b[1]));
}

__global__ void __launch_bounds__(256, 2)
sim_kernel(const float* __restrict__ tok, float* __restrict__ sim_out_arg) {
    __shared__ float rnA[128], rnB[128];
    __shared__ float As[2][128 * SSTR];
    __shared__ float Bs[2][128 * SSTR];

    float* sim_out = sim_out_arg ? sim_out_arg : g_sim;
    int b  = blockIdx.y;
    int ti = blockIdx.x >> 1, tj = blockIdx.x & 1;
    int i0 = ti * 128, j0 = tj * 128;
    bool diag = (ti == tj);
    int tid  = threadIdx.x;
    int lane = tid & 31, warp = tid >> 5;
    int wm = warp >> 2, wn = warp & 3;
    int g4 = lane >> 2, t4 = lane & 3;

    if (tid < 128)        rnA[tid] = (i0 + tid < NN) ? g_rnorm[b * NN + i0 + tid] : 0.f;
    else { int r = tid - 128;
                          rnB[r]   = (j0 + r   < NN) ? g_rnorm[b * NN + j0 + r]   : 0.f; }
    __syncthreads();

    float acc[4][4][4];
    #pragma unroll
    for (int ma = 0; ma < 4; ma++)
        #pragma unroll
        for (int na = 0; na < 4; na++)
            #pragma unroll
            for (int q = 0; q < 4; q++) acc[ma][na][q] = 0.f;

    const float* tokb = tok + (size_t)b * NN * DD;
    int frow0 = (tid >> 2);          // fill rows: it*64 + frow0
    int fcol  = (tid & 3) * 4;       // k-offset within chunk

    float4 pa[2], pb[2];
    // prefetch chunk 0
    #pragma unroll
    for (int it = 0; it < 2; it++) {
        int row = it * 64 + frow0;
        pa[it] = (i0 + row < NN) ? *(const float4*)(tokb + (size_t)(i0 + row) * DD + fcol)
                                 : make_float4(0.f, 0.f, 0.f, 0.f);
        if (!diag)
            pb[it] = (j0 + row < NN) ? *(const float4*)(tokb + (size_t)(j0 + row) * DD + fcol)
                                     : make_float4(0.f, 0.f, 0.f, 0.f);
    }

    for (int c = 0; c < NCH; c++) {
        float* A = As[c & 1];
        float* Bm = diag ? As[c & 1] : Bs[c & 1];

        // store prefetched chunk (tf32-rounded, rnorm folded in)
        #pragma unroll
        for (int it = 0; it < 2; it++) {
            int row = it * 64 + frow0;
            float rs = rnA[row];
            float4 v = pa[it];
            *(float4*)&A[row * SSTR + fcol] =
                make_float4(to_tf32(v.x * rs), to_tf32(v.y * rs),
                            to_tf32(v.z * rs), to_tf32(v.w * rs));
            if (!diag) {
                float rb = rnB[row];
                float4 w = pb[it];
                *(float4*)&Bs[c & 1][row * SSTR + fcol] =
                    make_float4(to_tf32(w.x * rb), to_tf32(w.y * rb),
                                to_tf32(w.z * rb), to_tf32(w.w * rb));
            }
        }
        __syncthreads();

        // prefetch next chunk (global loads overlap with the MMA below)
        if (c + 1 < NCH) {
            int koff = (c + 1) * KC + fcol;
            #pragma unroll
            for (int it = 0; it < 2; it++) {
                int row = it * 64 + frow0;
                pa[it] = (i0 + row < NN) ? *(const float4*)(tokb + (size_t)(i0 + row) * DD + koff)
                                         : make_float4(0.f, 0.f, 0.f, 0.f);
                if (!diag)
                    pb[it] = (j0 + row < NN) ? *(const float4*)(tokb + (size_t)(j0 + row) * DD + koff)
                                             : make_float4(0.f, 0.f, 0.f, 0.f);
            }
        }

        // compute: 2 k-slices of 8
        #pragma unroll
        for (int ks = 0; ks < 2; ks++) {
            int kb = ks * 8 + t4;
            unsigned afr[4][4];
            #pragma unroll
            for (int ma = 0; ma < 4; ma++) {
                int r = wm * 64 + ma * 16 + g4;
                afr[ma][0] = __float_as_uint(A[r * SSTR + kb]);
                afr[ma][1] = __float_as_uint(A[(r + 8) * SSTR + kb]);
                afr[ma][2] = __float_as_uint(A[r * SSTR + kb + 4]);
                afr[ma][3] = __float_as_uint(A[(r + 8) * SSTR + kb + 4]);
            }
            unsigned bfr[4][2];
            #pragma unroll
            for (int na = 0; na < 4; na++) {
                int cidx = wn * 32 + na * 8 + g4;
                bfr[na][0] = __float_as_uint(Bm[cidx * SSTR + kb]);
                bfr[na][1] = __float_as_uint(Bm[cidx * SSTR + kb + 4]);
            }
            #pragma unroll
            for (int ma = 0; ma < 4; ma++)
                #pragma unroll
                for (int na = 0; na < 4; na++)
                    mma_tf32(acc[ma][na], afr[ma], bfr[na]);
        }
    }

    // epilogue: coalesced float2 stores, zero diagonal on diag quadrants
    #pragma unroll
    for (int ma = 0; ma < 4; ma++) {
        #pragma unroll
        for (int na = 0; na < 4; na++) {
            int gj = j0 + wn * 32 + na * 8 + 2 * t4;
            if (gj >= NN) continue;
            #pragma unroll
            for (int h = 0; h < 2; h++) {
                int gi = i0 + wm * 64 + ma * 16 + g4 + h * 8;
                if (gi >= NN) continue;
                float v0 = acc[ma][na][h * 2 + 0];
                float v1 = acc[ma][na][h * 2 + 1];
                if (diag) {
                    if (gi == gj)     v0 = 0.f;
                    if (gi == gj + 1) v1 = 0.f;
                }
                *(float2*)&sim_out[((size_t)b * NN + gi) * NN + gj] = make_float2(v0, v1);
            }
        }
    }
}

// ---------------- kernel 5: grouping (fast path for empty adjacency) ---------
__global__ void __launch_bounds__(256, 1)
group_kernel(const float* __restrict__ sim_in_arg, float* out_gids) {
    int b = blockIdx.x, tid = threadIdx.x;
    const float* sim_in = sim_in_arg ? sim_in_arg : g_sim;
    __shared__ unsigned adj[NN][8];
    __shared__ float simp[NN];
    __shared__ int   sgid[NN];
    __shared__ float denom[NN];
    __shared__ int   cnt[NN];
    __shared__ int   off[NN + 1];
    __shared__ int   cur[NN];
    __shared__ unsigned assigned[8], reach[8], nxt[8];
    __shared__ int s_changed, s_ng, s_any;

    for (int i = tid; i < NN * 8; i += 256) (&adj[0][0])[i] = 0u;
    for (int i = tid; i < NN; i += 256) {
        simp[i] = g_imp[b * NN + i];
        cnt[i] = 0;
        denom[i] = EPSF;
    }
    if (tid < 8) assigned[tid] = 0u;
    if (tid == 0) { s_ng = 0; s_any = 0; }
    __syncthreads();

    const float* simb = sim_in + (size_t)b * NN * NN;
    for (int idx = tid; idx < NN * NN; idx += 256) {
        int i = idx / NN, j = idx - i * NN;
        float sv = simb[idx];
        if (sv > 0.9f && (1.0f - simp[i]) > 0.5f) {
            atomicOr(&adj[i][j >> 5], 1u << (j & 31));
            s_any = 1;
        }
    }
    __syncthreads();

    if (s_any == 0) {
        for (int i = tid; i < NN; i += 256) sgid[i] = i;
        if (tid == 0) s_ng = NN;
        __syncthreads();
    } else {
        for (int r = 0; r < NN; r++) {
            if ((assigned[r >> 5] >> (r & 31)) & 1u) continue;
            if (tid < 8) reach[tid] = (tid == (r >> 5)) ? (1u << (r & 31)) : 0u;
            __syncthreads();
            while (true) {
                if (tid < 8) nxt[tid] = 0u;
                if (tid == 0) s_changed = 0;
                __syncthreads();
                for (int i = tid; i < NN; i += 256) {
                    if ((reach[i >> 5] >> (i & 31)) & 1u) {
                        #pragma unroll
                        for (int w = 0; w < 7; w++) {
                            unsigned v = adj[i][w];
                            if (v) atomicOr(&nxt[w], v);
                        }
                    }
                }
                __syncthreads();
                if (tid < 8) {
                    unsigned nv = reach[tid] | (nxt[tid] & ~assigned[tid]);
                    if (nv != reach[tid]) s_changed = 1;
                    nxt[tid] = nv;
                }
                __syncthreads();
                if (tid < 8) reach[tid] = nxt[tid];
                __syncthreads();
                if (!s_changed) break;
            }
            int gid = s_ng;
            for (int i = tid; i < NN; i += 256)
                if ((reach[i >> 5] >> (i & 31)) & 1u) sgid[i] = gid;
            if (tid < 8) assigned[tid] |= reach[tid];
            __syncthreads();
            if (tid == 0) s_ng = gid + 1;
            __syncthreads();
        }
    }

    for (int i = tid; i < NN; i += 256) atomicAdd(&denom[sgid[i]], simp[i]);
    __syncthreads();
    for (int i = tid; i < NN; i += 256) {
        g_w[b * NN + i]    = simp[i] / denom[sgid[i]];
        g_gids[b * NN + i] = sgid[i];
        if (out_gids) out_gids[b * NN + i] = (float)sgid[i];
        atomicAdd(&cnt[sgid[i]], 1);
    }
    __syncthreads();
    if (tid == 0) {
        off[0] = 0;
        for (int g = 0; g < NN; g++) off[g + 1] = off[g] + cnt[g];
    }
    __syncthreads();
    for (int g = tid; g < NN; g += 256) cur[g] = off[g];
    for (int g = tid; g < NN + 1; g += 256) g_goff[b * (NN + 1) + g] = off[g];
    __syncthreads();
    for (int i = tid; i < NN; i += 256) {
        int g = sgid[i];
        int pos = atomicAdd(&cur[g], 1);
        g_members[b * NN + pos] = i;
    }
}

// ---------------- kernel 6: merged tokens (CSR gather, float4) ----------------
__global__ void __launch_bounds__(192)
merge_kernel(const float* __restrict__ tok, float* __restrict__ out) {
    int b = blockIdx.y, g = blockIdx.x, tid = threadIdx.x;
    int o0 = g_goff[b * (NN + 1) + g];
    int o1 = g_goff[b * (NN + 1) + g + 1];
    float4 a = make_float4(0.f, 0.f, 0.f, 0.f);
    const float4* tokb = (const float4*)(tok + (size_t)b * NN * DD);
    for (int k = o0; k < o1; k++) {
        int i = g_members[b * NN + k];
        float wv = g_w[b * NN + i];
        float4 v = tokb[(size_t)i * (DD / 4) + tid];
        a.x += v.x * wv; a.y += v.y * wv; a.z += v.z * wv; a.w += v.w * wv;
    }
    ((float4*)out)[((size_t)b * NN + g) * (DD / 4) + tid] = a;
}

// ---------------- launch ------------------------------------------------------
extern "C" void kernel_launch(void* const* d_in, const int* in_sizes, int n_in,
                              void* d_out, int out_size) {
    const float* tokens = (const float*)d_in[0];
    const float* motion = (const float*)d_in[1];
    const float* sal    = (const float*)d_in[2];
    float* out = (float*)d_out;

    const long long SZ_M = (long long)BB * NN * DD;   // 19267584
    const long long SZ_S = (long long)BB * NN * NN;   //  4917248
    const long long SZ_I = (long long)BB * NN;        //    25088
    long long osz = (long long)out_size;

    float* out_sim  = (osz >= SZ_M + SZ_S)            ? out + SZ_M               : nullptr;
    float* out_imp  = (osz >= SZ_M + SZ_S + SZ_I)     ? out + SZ_M + SZ_S        : nullptr;
    float* out_gids = (osz >= SZ_M + SZ_S + 2 * SZ_I) ? out + SZ_M + SZ_S + SZ_I : nullptr;

    gmax_init_kernel<<<1, 32>>>();
    gmax_kernel<<<dim3(16, 2), 256>>>(motion, sal, NTOK);
    imp_kernel<<<BB, 256>>>(motion, sal, out_imp);
    rnorm_kernel<<<(NTOK * 32 + 255) / 256, 256>>>(tokens);
    sim_kernel<<<dim3(4, BB), 256>>>(tokens, out_sim);
    group_kernel<<<BB, 256>>>(out_sim, out_gids);
    merge_kernel<<<dim3(NN, BB), 192>>>(tokens, out);
}

// round 8
// speedup vs baseline: 3.3327x; 1.1973x over previous
#include <cuda_runtime.h>
#include <cuda_bf16.h>
#include <math_constants.h>
#include <cstdint>

// Problem constants
#define BB   128
#define NN   196
#define DD   768
#define NTOK (BB * NN)      // 25088
#define EPSF 1e-6f
#define EMAX 2048           // per-batch edge-list capacity

// ---------------- static device scratch (no allocations allowed) -------------
__device__ float    g_sim[(size_t)BB * NN * NN];   // fallback only (~19.7 MB)
__device__ float    g_rnorm[NTOK];
__device__ float    g_imp[NTOK];
__device__ float    g_w[NTOK];
__device__ int      g_gids[NTOK];
__device__ int      g_members[NTOK];
__device__ int      g_goff[BB * (NN + 1)];
__device__ unsigned g_gmax_u[2];
__device__ int      g_edge_cnt[BB];
__device__ int      g_edges[BB * EMAX];

// ---------------- kernel 0/1: init + global max of motion / saliency ----------
__global__ void gmax_init_kernel() {
    if (threadIdx.x < 2) g_gmax_u[threadIdx.x] = 0u;
    if (threadIdx.x < BB) g_edge_cnt[threadIdx.x] = 0;
}
__global__ void gmax_kernel(const float* __restrict__ m,
                            const float* __restrict__ s, int n) {
    const float* p = (blockIdx.y == 0) ? m : s;
    float mx = 0.f;
    for (int i = blockIdx.x * blockDim.x + threadIdx.x; i < n; i += gridDim.x * blockDim.x)
        mx = fmaxf(mx, p[i]);
    #pragma unroll
    for (int o = 16; o; o >>= 1) mx = fmaxf(mx, __shfl_xor_sync(0xffffffffu, mx, o));
    __shared__ float sh[8];
    int lane = threadIdx.x & 31, warp = threadIdx.x >> 5;
    if (lane == 0) sh[warp] = mx;
    __syncthreads();
    if (threadIdx.x == 0) {
        float v = sh[0];
        for (int w = 1; w < (int)(blockDim.x >> 5); w++) v = fmaxf(v, sh[w]);
        atomicMax(&g_gmax_u[blockIdx.y], __float_as_uint(v));
    }
}

// ---------------- kernel 2: importance per batch -----------------------------
__global__ void imp_kernel(const float* __restrict__ m,
                           const float* __restrict__ s,
                           float* out_imp) {
    int b = blockIdx.x, t = threadIdx.x;
    __shared__ float lo[256], hi[256];
    bool valid = (t < NN);
    float v = 0.f;
    if (valid) {
        float gm0 = __uint_as_float(g_gmax_u[0]);
        float gm1 = __uint_as_float(g_gmax_u[1]);
        float mn = m[b * NN + t] / (gm0 + EPSF);
        float sn = s[b * NN + t] / (gm1 + EPSF);
        v = 0.5f * mn + 0.5f * sn;
    }
    lo[t] = valid ? v :  CUDART_INF_F;
    hi[t] = valid ? v : -CUDART_INF_F;
    __syncthreads();
    for (int o = 128; o; o >>= 1) {
        if (t < o) { lo[t] = fminf(lo[t], lo[t + o]); hi[t] = fmaxf(hi[t], hi[t + o]); }
        __syncthreads();
    }
    float l = lo[0], h = hi[0];
    if (valid) {
        float r = (v - l) / (h - l + EPSF);
        g_imp[b * NN + t] = r;
        if (out_imp) out_imp[b * NN + t] = r;
    }
}

// ---------------- kernel 3: reciprocal token norms (float4) -------------------
__global__ void rnorm_kernel(const float* __restrict__ tok) {
    int warp = (blockIdx.x * blockDim.x + threadIdx.x) >> 5;
    int lane = threadIdx.x & 31;
    if (warp >= NTOK) return;
    const float4* tr = (const float4*)(tok + (size_t)warp * DD);
    float acc = 0.f;
    #pragma unroll
    for (int it = 0; it < 6; it++) {
        float4 v = tr[lane + it * 32];
        acc += v.x * v.x + v.y * v.y + v.z * v.z + v.w * v.w;
    }
    #pragma unroll
    for (int o = 16; o; o >>= 1) acc += __shfl_xor_sync(0xffffffffu, acc, o);
    if (lane == 0) {
        float nrm = fmaxf(sqrtf(acc), 1e-12f);
        g_rnorm[warp] = 1.0f / nrm;
    }
}

// ---------------- kernel 4: cosine similarity via tf32 mma.sync --------------
// 3 CTAs per batch: (0,0) diag, (0,1) offdiag (+mirror via smem transpose),
// (1,1) diag. 8 warps (2x4), warp tile 64x32, K-chunk 16, reg-prefetch +
// double-buffered smem. Edge detection (>0.9) fused into epilogue.
#define KC   16
#define NCH  (DD / KC)     // 48
#define SSTR 20            // smem row stride (floats): conflict-free frag LDS

__device__ __forceinline__ float to_tf32(float x) {
    float r; asm("cvt.rna.tf32.f32 %0, %1;" : "=f"(r) : "f"(x)); return r;
}
__device__ __forceinline__ void mma_tf32(float (&d)[4], const unsigned (&a)[4],
                                         const unsigned (&b)[2]) {
    asm volatile("mma.sync.aligned.m16n8k8.row.col.f32.tf32.tf32.f32 "
                 "{%0,%1,%2,%3}, {%4,%5,%6,%7}, {%8,%9}, {%0,%1,%2,%3};\n"
                 : "+f"(d[0]), "+f"(d[1]), "+f"(d[2]), "+f"(d[3])
                 : "r"(a[0]), "r"(a[1]), "r"(a[2]), "r"(a[3]),
                   "r"(b[0]), "r"(b[1]));
}
__device__ __forceinline__ void rec_edge(int b, int i, int j) {
    int slot = atomicAdd(&g_edge_cnt[b], 1);
    if (slot < EMAX) g_edges[b * EMAX + slot] = (i << 8) | j;
}

__global__ void __launch_bounds__(256)
sim_kernel(const float* __restrict__ tok, float* __restrict__ sim_out_arg) {
    __shared__ float rnA[128], rnB[128];
    __shared__ __align__(16) float As[2][128 * SSTR];
    __shared__ __align__(16) float Bs[2][128 * SSTR];

    float* sim_out = sim_out_arg ? sim_out_arg : g_sim;
    int b  = blockIdx.y;
    int bx = blockIdx.x;                 // 0:(0,0)  1:(0,1)+mirror  2:(1,1)
    int ti = (bx == 2) ? 1 : 0;
    int tj = (bx >= 1) ? 1 : 0;
    int i0 = ti * 128, j0 = tj * 128;
    bool diag   = (ti == tj);
    bool mirror = (bx == 1);
    int tid  = threadIdx.x;
    int lane = tid & 31, warp = tid >> 5;
    int wm = warp >> 2, wn = warp & 3;
    int g4 = lane >> 2, t4 = lane & 3;

    if (tid < 128)        rnA[tid] = (i0 + tid < NN) ? g_rnorm[b * NN + i0 + tid] : 0.f;
    else { int r = tid - 128;
                          rnB[r]   = (j0 + r   < NN) ? g_rnorm[b * NN + j0 + r]   : 0.f; }
    __syncthreads();

    float acc[4][4][4];
    #pragma unroll
    for (int ma = 0; ma < 4; ma++)
        #pragma unroll
        for (int na = 0; na < 4; na++)
            #pragma unroll
            for (int q = 0; q < 4; q++) acc[ma][na][q] = 0.f;

    const float* tokb = tok + (size_t)b * NN * DD;
    int frow0 = (tid >> 2);
    int fcol  = (tid & 3) * 4;

    float4 pa[2], pb[2];
    #pragma unroll
    for (int it = 0; it < 2; it++) {
        int row = it * 64 + frow0;
        pa[it] = (i0 + row < NN) ? *(const float4*)(tokb + (size_t)(i0 + row) * DD + fcol)
                                 : make_float4(0.f, 0.f, 0.f, 0.f);
        if (!diag)
            pb[it] = (j0 + row < NN) ? *(const float4*)(tokb + (size_t)(j0 + row) * DD + fcol)
                                     : make_float4(0.f, 0.f, 0.f, 0.f);
    }

    for (int c = 0; c < NCH; c++) {
        float* A = As[c & 1];
        float* Bm = diag ? As[c & 1] : Bs[c & 1];

        #pragma unroll
        for (int it = 0; it < 2; it++) {
            int row = it * 64 + frow0;
            float rs = rnA[row];
            float4 v = pa[it];
            *(float4*)&A[row * SSTR + fcol] =
                make_float4(to_tf32(v.x * rs), to_tf32(v.y * rs),
                            to_tf32(v.z * rs), to_tf32(v.w * rs));
            if (!diag) {
                float rb = rnB[row];
                float4 w = pb[it];
                *(float4*)&Bs[c & 1][row * SSTR + fcol] =
                    make_float4(to_tf32(w.x * rb), to_tf32(w.y * rb),
                                to_tf32(w.z * rb), to_tf32(w.w * rb));
            }
        }
        __syncthreads();

        if (c + 1 < NCH) {
            int koff = (c + 1) * KC + fcol;
            #pragma unroll
            for (int it = 0; it < 2; it++) {
                int row = it * 64 + frow0;
                pa[it] = (i0 + row < NN) ? *(const float4*)(tokb + (size_t)(i0 + row) * DD + koff)
                                         : make_float4(0.f, 0.f, 0.f, 0.f);
                if (!diag)
                    pb[it] = (j0 + row < NN) ? *(const float4*)(tokb + (size_t)(j0 + row) * DD + koff)
                                             : make_float4(0.f, 0.f, 0.f, 0.f);
            }
        }

        #pragma unroll
        for (int ks = 0; ks < 2; ks++) {
            int kb = ks * 8 + t4;
            unsigned afr[4][4];
            #pragma unroll
            for (int ma = 0; ma < 4; ma++) {
                int r = wm * 64 + ma * 16 + g4;
                afr[ma][0] = __float_as_uint(A[r * SSTR + kb]);
                afr[ma][1] = __float_as_uint(A[(r + 8) * SSTR + kb]);
                afr[ma][2] = __float_as_uint(A[r * SSTR + kb + 4]);
                afr[ma][3] = __float_as_uint(A[(r + 8) * SSTR + kb + 4]);
            }
            unsigned bfr[4][2];
            #pragma unroll
            for (int na = 0; na < 4; na++) {
                int cidx = wn * 32 + na * 8 + g4;
                bfr[na][0] = __float_as_uint(Bm[cidx * SSTR + kb]);
                bfr[na][1] = __float_as_uint(Bm[cidx * SSTR + kb + 4]);
            }
            #pragma unroll
            for (int ma = 0; ma < 4; ma++)
                #pragma unroll
                for (int na = 0; na < 4; na++)
                    mma_tf32(acc[ma][na], afr[ma], bfr[na]);
        }
        __syncthreads();
    }

    // ---- epilogue 1: this quadrant's tile (coalesced float2) ----
    #pragma unroll
    for (int ma = 0; ma < 4; ma++) {
        #pragma unroll
        for (int na = 0; na < 4; na++) {
            int gj = j0 + wn * 32 + na * 8 + 2 * t4;
            if (gj >= NN) continue;
            #pragma unroll
            for (int h = 0; h < 2; h++) {
                int gi = i0 + wm * 64 + ma * 16 + g4 + h * 8;
                if (gi >= NN) continue;
                float v0 = acc[ma][na][h * 2 + 0];
                float v1 = acc[ma][na][h * 2 + 1];
                if (diag) {
                    if (gi == gj)     v0 = 0.f;
                    if (gi == gj + 1) v1 = 0.f;
                }
                if (v0 > 0.9f) rec_edge(b, gi, gj);
                if (v1 > 0.9f && gj + 1 < NN) rec_edge(b, gi, gj + 1);
                *(float2*)&sim_out[((size_t)b * NN + gi) * NN + gj] = make_float2(v0, v1);
            }
        }
    }

    // ---- epilogue 2: mirror (1,0) via smem transpose (off-diag CTA only) ----
    if (mirror) {
        float* S = &As[0][0];            // 32 x 132 staging (16.9 KB)
        #pragma unroll
        for (int cb = 0; cb < 3; cb++) {   // local col chunks; cb=3 all OOB
            __syncthreads();
            if (wn == cb) {
                #pragma unroll
                for (int ma = 0; ma < 4; ma++)
                    #pragma unroll
                    for (int na = 0; na < 4; na++)
                        #pragma unroll
                        for (int q = 0; q < 4; q++) {
                            int jc = na * 8 + 2 * t4 + (q & 1);
                            int il = wm * 64 + ma * 16 + g4 + 8 * (q >> 1);
                            S[jc * 132 + il] = acc[ma][na][q];
                        }
            }
            __syncthreads();
            #pragma unroll
            for (int it = 0; it < 4; it++) {
                int jc = it * 8 + (tid >> 5);
                int gj = 128 + cb * 32 + jc;       // mirror row
                if (gj >= NN) continue;
                int i = (tid & 31) * 4;
                float4 v = *(float4*)&S[jc * 132 + i];
                if (v.x > 0.9f) rec_edge(b, gj, i + 0);
                if (v.y > 0.9f) rec_edge(b, gj, i + 1);
                if (v.z > 0.9f) rec_edge(b, gj, i + 2);
                if (v.w > 0.9f) rec_edge(b, gj, i + 3);
                *(float4*)&sim_out[((size_t)b * NN + gj) * NN + i] = v;
            }
        }
    }
}

// ---------------- kernel 5: grouping (edge-list driven) ----------------------
__global__ void __launch_bounds__(256, 1)
group_kernel(const float* __restrict__ sim_in_arg, float* out_gids) {
    int b = blockIdx.x, tid = threadIdx.x;
    const float* sim_in = sim_in_arg ? sim_in_arg : g_sim;
    __shared__ unsigned adj[NN][8];
    __shared__ float simp[NN];
    __shared__ int   sgid[NN];
    __shared__ float denom[NN];
    __shared__ int   cnt[NN];
    __shared__ int   off[NN + 1];
    __shared__ int   cur[NN];
    __shared__ unsigned assigned[8], reach[8], nxt[8];
    __shared__ int s_changed, s_ng, s_any;

    int ecnt = g_edge_cnt[b];

    for (int i = tid; i < NN; i += 256) {
        simp[i] = g_imp[b * NN + i];
        cnt[i] = 0;
        denom[i] = EPSF;
    }
    if (tid < 8) assigned[tid] = 0u;
    if (tid == 0) { s_ng = 0; s_any = 0; }
    __syncthreads();

    if (ecnt == 0) {
        // no candidate edges anywhere in this batch: singleton groups
        for (int i = tid; i < NN; i += 256) sgid[i] = i;
        if (tid == 0) s_ng = NN;
        __syncthreads();
    } else {
        for (int i = tid; i < NN * 8; i += 256) (&adj[0][0])[i] = 0u;
        __syncthreads();
        if (ecnt <= EMAX) {
            // build adjacency from recorded edges (order-independent bitmask)
            for (int e = tid; e < ecnt; e += 256) {
                int pk = g_edges[b * EMAX + e];
                int i = pk >> 8, j = pk & 255;
                if (j < NN && (1.0f - simp[i]) > 0.5f) {
                    atomicOr(&adj[i][j >> 5], 1u << (j & 31));
                    s_any = 1;
                }
            }
        } else {
            // overflow: full scan fallback
            const float* simb = sim_in + (size_t)b * NN * NN;
            for (int idx = tid; idx < NN * NN; idx += 256) {
                int i = idx / NN, j = idx - i * NN;
                float sv = simb[idx];
                if (sv > 0.9f && (1.0f - simp[i]) > 0.5f) {
                    atomicOr(&adj[i][j >> 5], 1u << (j & 31));
                    s_any = 1;
                }
            }
        }
        __syncthreads();

        if (s_any == 0) {
            for (int i = tid; i < NN; i += 256) sgid[i] = i;
            if (tid == 0) s_ng = NN;
            __syncthreads();
        } else {
            for (int r = 0; r < NN; r++) {
                if ((assigned[r >> 5] >> (r & 31)) & 1u) continue;
                if (tid < 8) reach[tid] = (tid == (r >> 5)) ? (1u << (r & 31)) : 0u;
                __syncthreads();
                while (true) {
                    if (tid < 8) nxt[tid] = 0u;
                    if (tid == 0) s_changed = 0;
                    __syncthreads();
                    for (int i = tid; i < NN; i += 256) {
                        if ((reach[i >> 5] >> (i & 31)) & 1u) {
                            #pragma unroll
                            for (int w = 0; w < 7; w++) {
                                unsigned v = adj[i][w];
                                if (v) atomicOr(&nxt[w], v);
                            }
                        }
                    }
                    __syncthreads();
                    if (tid < 8) {
                        unsigned nv = reach[tid] | (nxt[tid] & ~assigned[tid]);
                        if (nv != reach[tid]) s_changed = 1;
                        nxt[tid] = nv;
                    }
                    __syncthreads();
                    if (tid < 8) reach[tid] = nxt[tid];
                    __syncthreads();
                    if (!s_changed) break;
                }
                int gid = s_ng;
                for (int i = tid; i < NN; i += 256)
                    if ((reach[i >> 5] >> (i & 31)) & 1u) sgid[i] = gid;
                if (tid < 8) assigned[tid] |= reach[tid];
                __syncthreads();
                if (tid == 0) s_ng = gid + 1;
                __syncthreads();
            }
        }
    }

    for (int i = tid; i < NN; i += 256) atomicAdd(&denom[sgid[i]], simp[i]);
    __syncthreads();
    for (int i = tid; i < NN; i += 256) {
        g_w[b * NN + i]    = simp[i] / denom[sgid[i]];
        g_gids[b * NN + i] = sgid[i];
        if (out_gids) out_gids[b * NN + i] = (float)sgid[i];
        atomicAdd(&cnt[sgid[i]], 1);
    }
    __syncthreads();
    if (tid == 0) {
        off[0] = 0;
        for (int g = 0; g < NN; g++) off[g + 1] = off[g] + cnt[g];
    }
    __syncthreads();
    for (int g = tid; g < NN; g += 256) cur[g] = off[g];
    for (int g = tid; g < NN + 1; g += 256) g_goff[b * (NN + 1) + g] = off[g];
    __syncthreads();
    for (int i = tid; i < NN; i += 256) {
        int g = sgid[i];
        int pos = atomicAdd(&cur[g], 1);
        g_members[b * NN + pos] = i;
    }
}

// ---------------- kernel 6: merged tokens (CSR gather, float4) ----------------
__global__ void __launch_bounds__(192)
merge_kernel(const float* __restrict__ tok, float* __restrict__ out) {
    int b = blockIdx.y, g = blockIdx.x, tid = threadIdx.x;
    int o0 = g_goff[b * (NN + 1) + g];
    int o1 = g_goff[b * (NN + 1) + g + 1];
    float4 a = make_float4(0.f, 0.f, 0.f, 0.f);
    const float4* tokb = (const float4*)(tok + (size_t)b * NN * DD);
    for (int k = o0; k < o1; k++) {
        int i = g_members[b * NN + k];
        float wv = g_w[b * NN + i];
        float4 v = tokb[(size_t)i * (DD / 4) + tid];
        a.x += v.x * wv; a.y += v.y * wv; a.z += v.z * wv; a.w += v.w * wv;
    }
    ((float4*)out)[((size_t)b * NN + g) * (DD / 4) + tid] = a;
}

// ---------------- launch ------------------------------------------------------
extern "C" void kernel_launch(void* const* d_in, const int* in_sizes, int n_in,
                              void* d_out, int out_size) {
    const float* tokens = (const float*)d_in[0];
    const float* motion = (const float*)d_in[1];
    const float* sal    = (const float*)d_in[2];
    float* out = (float*)d_out;

    const long long SZ_M = (long long)BB * NN * DD;   // 19267584
    const long long SZ_S = (long long)BB * NN * NN;   //  4917248
    const long long SZ_I = (long long)BB * NN;        //    25088
    long long osz = (long long)out_size;

    float* out_sim  = (osz >= SZ_M + SZ_S)            ? out + SZ_M               : nullptr;
    float* out_imp  = (osz >= SZ_M + SZ_S + SZ_I)     ? out + SZ_M + SZ_S        : nullptr;
    float* out_gids = (osz >= SZ_M + SZ_S + 2 * SZ_I) ? out + SZ_M + SZ_S + SZ_I : nullptr;

    gmax_init_kernel<<<1, 128>>>();
    gmax_kernel<<<dim3(16, 2), 256>>>(motion, sal, NTOK);
    imp_kernel<<<BB, 256>>>(motion, sal, out_imp);
    rnorm_kernel<<<(NTOK * 32 + 255) / 256, 256>>>(tokens);
    sim_kernel<<<dim3(3, BB), 256>>>(tokens, out_sim);
    group_kernel<<<BB, 256>>>(out_sim, out_gids);
    merge_kernel<<<dim3(NN, BB), 192>>>(tokens, out);
}

// round 9
// speedup vs baseline: 3.7855x; 1.1359x over previous
#include <cuda_runtime.h>
#include <cuda_bf16.h>
#include <math_constants.h>
#include <cstdint>

// Problem constants
#define BB   128
#define NN   196
#define DD   768
#define NTOK (BB * NN)      // 25088
#define EPSF 1e-6f
#define EMAX 2048           // per-batch edge-list capacity

// ---------------- static device scratch (no allocations allowed) -------------
__device__ float    g_sim[(size_t)BB * NN * NN];   // fallback only (~19.7 MB)
__device__ float    g_imp[NTOK];
__device__ float    g_w[NTOK];
__device__ int      g_gids[NTOK];
__device__ int      g_members[NTOK];
__device__ int      g_goff[BB * (NN + 1)];
__device__ unsigned g_gmax_u[2];
__device__ int      g_edge_cnt[BB];
__device__ int      g_edges[BB * EMAX];

// ---------------- kernel 1: global max of motion / saliency (2 blocks) -------
// Block 0 also zeroes the per-batch edge counters. Plain store, no atomics.
__global__ void __launch_bounds__(1024)
gmax2_kernel(const float* __restrict__ m, const float* __restrict__ s, int n) {
    if (blockIdx.x == 0 && threadIdx.x < BB) g_edge_cnt[threadIdx.x] = 0;
    const float* p = (blockIdx.x == 0) ? m : s;
    float mx = 0.f;
    for (int i = threadIdx.x; i < n; i += 1024) mx = fmaxf(mx, p[i]);
    #pragma unroll
    for (int o = 16; o; o >>= 1) mx = fmaxf(mx, __shfl_xor_sync(0xffffffffu, mx, o));
    __shared__ float sh[32];
    int lane = threadIdx.x & 31, warp = threadIdx.x >> 5;
    if (lane == 0) sh[warp] = mx;
    __syncthreads();
    if (warp == 0) {
        float v = (lane < 32) ? sh[lane] : 0.f;
        #pragma unroll
        for (int o = 16; o; o >>= 1) v = fmaxf(v, __shfl_xor_sync(0xffffffffu, v, o));
        if (lane == 0) g_gmax_u[blockIdx.x] = __float_as_uint(v);
    }
}

// ---------------- kernel 2: importance per batch -----------------------------
__global__ void imp_kernel(const float* __restrict__ m,
                           const float* __restrict__ s,
                           float* out_imp) {
    int b = blockIdx.x, t = threadIdx.x;
    __shared__ float lo[256], hi[256];
    bool valid = (t < NN);
    float v = 0.f;
    if (valid) {
        float gm0 = __uint_as_float(g_gmax_u[0]);
        float gm1 = __uint_as_float(g_gmax_u[1]);
        float mn = m[b * NN + t] / (gm0 + EPSF);
        float sn = s[b * NN + t] / (gm1 + EPSF);
        v = 0.5f * mn + 0.5f * sn;
    }
    lo[t] = valid ? v :  CUDART_INF_F;
    hi[t] = valid ? v : -CUDART_INF_F;
    __syncthreads();
    for (int o = 128; o; o >>= 1) {
        if (t < o) { lo[t] = fminf(lo[t], lo[t + o]); hi[t] = fmaxf(hi[t], hi[t + o]); }
        __syncthreads();
    }
    float l = lo[0], h = hi[0];
    if (valid) {
        float r = (v - l) / (h - l + EPSF);
        g_imp[b * NN + t] = r;
        if (out_imp) out_imp[b * NN + t] = r;
    }
}

// ---------------- kernel 4: cosine similarity via tf32 mma.sync --------------
// 3 CTAs per batch: (0,0) diag, (0,1) offdiag (+mirror via smem transpose),
// (1,1) diag. 8 warps (2x4), warp tile 64x32, K-chunk 16, reg-prefetch +
// double-buffered smem, ONE barrier per chunk. Row norms accumulated in the
// fill loop (sum of squares), applied at the epilogue. Edge detection fused.
#define KC   16
#define NCH  (DD / KC)     // 48
#define SSTR 20            // smem row stride (floats): conflict-free frag LDS

__device__ __forceinline__ float to_tf32(float x) {
    float r; asm("cvt.rna.tf32.f32 %0, %1;" : "=f"(r) : "f"(x)); return r;
}
__device__ __forceinline__ void mma_tf32(float (&d)[4], const unsigned (&a)[4],
                                         const unsigned (&b)[2]) {
    asm volatile("mma.sync.aligned.m16n8k8.row.col.f32.tf32.tf32.f32 "
                 "{%0,%1,%2,%3}, {%4,%5,%6,%7}, {%8,%9}, {%0,%1,%2,%3};\n"
                 : "+f"(d[0]), "+f"(d[1]), "+f"(d[2]), "+f"(d[3])
                 : "r"(a[0]), "r"(a[1]), "r"(a[2]), "r"(a[3]),
                   "r"(b[0]), "r"(b[1]));
}
__device__ __forceinline__ void rec_edge(int b, int i, int j) {
    int slot = atomicAdd(&g_edge_cnt[b], 1);
    if (slot < EMAX) g_edges[b * EMAX + slot] = (i << 8) | j;
}

__global__ void __launch_bounds__(256)
sim_kernel(const float* __restrict__ tok, float* __restrict__ sim_out_arg) {
    __shared__ float rnA[128], rnB[128];
    __shared__ __align__(16) float As[2][128 * SSTR];
    __shared__ __align__(16) float Bs[2][128 * SSTR];

    float* sim_out = sim_out_arg ? sim_out_arg : g_sim;
    int b  = blockIdx.y;
    int bx = blockIdx.x;                 // 0:(0,0)  1:(0,1)+mirror  2:(1,1)
    int ti = (bx == 2) ? 1 : 0;
    int tj = (bx >= 1) ? 1 : 0;
    int i0 = ti * 128, j0 = tj * 128;
    bool diag   = (ti == tj);
    bool mirror = (bx == 1);
    int tid  = threadIdx.x;
    int lane = tid & 31, warp = tid >> 5;
    int wm = warp >> 2, wn = warp & 3;
    int g4 = lane >> 2, t4 = lane & 3;

    float acc[4][4][4];
    #pragma unroll
    for (int ma = 0; ma < 4; ma++)
        #pragma unroll
        for (int na = 0; na < 4; na++)
            #pragma unroll
            for (int q = 0; q < 4; q++) acc[ma][na][q] = 0.f;

    const float* tokb = tok + (size_t)b * NN * DD;
    int frow0 = (tid >> 2);
    int fcol  = (tid & 3) * 4;

    float ssa[2] = {0.f, 0.f}, ssb[2] = {0.f, 0.f};

    float4 pa[2], pb[2];
    #pragma unroll
    for (int it = 0; it < 2; it++) {
        int row = it * 64 + frow0;
        pa[it] = (i0 + row < NN) ? *(const float4*)(tokb + (size_t)(i0 + row) * DD + fcol)
                                 : make_float4(0.f, 0.f, 0.f, 0.f);
        if (!diag)
            pb[it] = (j0 + row < NN) ? *(const float4*)(tokb + (size_t)(j0 + row) * DD + fcol)
                                     : make_float4(0.f, 0.f, 0.f, 0.f);
    }

    for (int c = 0; c < NCH; c++) {
        float* A = As[c & 1];
        float* Bm = diag ? As[c & 1] : Bs[c & 1];

        #pragma unroll
        for (int it = 0; it < 2; it++) {
            int row = it * 64 + frow0;
            float4 v = pa[it];
            ssa[it] += v.x * v.x + v.y * v.y + v.z * v.z + v.w * v.w;
            *(float4*)&A[row * SSTR + fcol] =
                make_float4(to_tf32(v.x), to_tf32(v.y), to_tf32(v.z), to_tf32(v.w));
            if (!diag) {
                float4 w = pb[it];
                ssb[it] += w.x * w.x + w.y * w.y + w.z * w.z + w.w * w.w;
                *(float4*)&Bs[c & 1][row * SSTR + fcol] =
                    make_float4(to_tf32(w.x), to_tf32(w.y), to_tf32(w.z), to_tf32(w.w));
            }
        }
        __syncthreads();

        if (c + 1 < NCH) {
            int koff = (c + 1) * KC + fcol;
            #pragma unroll
            for (int it = 0; it < 2; it++) {
                int row = it * 64 + frow0;
                pa[it] = (i0 + row < NN) ? *(const float4*)(tokb + (size_t)(i0 + row) * DD + koff)
                                         : make_float4(0.f, 0.f, 0.f, 0.f);
                if (!diag)
                    pb[it] = (j0 + row < NN) ? *(const float4*)(tokb + (size_t)(j0 + row) * DD + koff)
                                             : make_float4(0.f, 0.f, 0.f, 0.f);
            }
        }

        #pragma unroll
        for (int ks = 0; ks < 2; ks++) {
            int kb = ks * 8 + t4;
            unsigned afr[4][4];
            #pragma unroll
            for (int ma = 0; ma < 4; ma++) {
                int r = wm * 64 + ma * 16 + g4;
                afr[ma][0] = __float_as_uint(A[r * SSTR + kb]);
                afr[ma][1] = __float_as_uint(A[(r + 8) * SSTR + kb]);
                afr[ma][2] = __float_as_uint(A[r * SSTR + kb + 4]);
                afr[ma][3] = __float_as_uint(A[(r + 8) * SSTR + kb + 4]);
            }
            unsigned bfr[4][2];
            #pragma unroll
            for (int na = 0; na < 4; na++) {
                int cidx = wn * 32 + na * 8 + g4;
                bfr[na][0] = __float_as_uint(Bm[cidx * SSTR + kb]);
                bfr[na][1] = __float_as_uint(Bm[cidx * SSTR + kb + 4]);
            }
            #pragma unroll
            for (int ma = 0; ma < 4; ma++)
                #pragma unroll
                for (int na = 0; na < 4; na++)
                    mma_tf32(acc[ma][na], afr[ma], bfr[na]);
        }
        // no trailing barrier needed: next fill writes the OTHER buffer, and
        // the reuse hazard (c+2 vs compute c) is fenced by the next barrier.
    }

    // ---- reduce per-row sum of squares -> reciprocal norms in smem ----
    #pragma unroll
    for (int it = 0; it < 2; it++) {
        float s = ssa[it];
        s += __shfl_xor_sync(0xffffffffu, s, 1);
        s += __shfl_xor_sync(0xffffffffu, s, 2);
        if (t4 == 0) rnA[it * 64 + frow0] = 1.0f / fmaxf(sqrtf(s), 1e-12f);
        if (!diag) {
            float t = ssb[it];
            t += __shfl_xor_sync(0xffffffffu, t, 1);
            t += __shfl_xor_sync(0xffffffffu, t, 2);
            if (t4 == 0) rnB[it * 64 + frow0] = 1.0f / fmaxf(sqrtf(t), 1e-12f);
        }
    }
    __syncthreads();
    const float* rnBp = diag ? rnA : rnB;

    // ---- epilogue 1: this quadrant's tile (coalesced float2, scaled) ----
    #pragma unroll
    for (int ma = 0; ma < 4; ma++) {
        #pragma unroll
        for (int na = 0; na < 4; na++) {
            int lj = wn * 32 + na * 8 + 2 * t4;
            int gj = j0 + lj;
            if (gj >= NN) continue;
            float rb0 = rnBp[lj], rb1 = rnBp[lj + 1];
            #pragma unroll
            for (int h = 0; h < 2; h++) {
                int li = wm * 64 + ma * 16 + g4 + h * 8;
                int gi = i0 + li;
                if (gi >= NN) continue;
                float ra = rnA[li];
                float v0 = acc[ma][na][h * 2 + 0] * ra * rb0;
                float v1 = acc[ma][na][h * 2 + 1] * ra * rb1;
                if (diag) {
                    if (gi == gj)     v0 = 0.f;
                    if (gi == gj + 1) v1 = 0.f;
                }
                if (v0 > 0.9f) rec_edge(b, gi, gj);
                if (v1 > 0.9f && gj + 1 < NN) rec_edge(b, gi, gj + 1);
                *(float2*)&sim_out[((size_t)b * NN + gi) * NN + gj] = make_float2(v0, v1);
            }
        }
    }

    // ---- epilogue 2: mirror (1,0) via smem transpose (off-diag CTA only) ----
    if (mirror) {
        float* S = &As[0][0];            // 32 x 132 staging
        #pragma unroll
        for (int cb = 0; cb < 3; cb++) {   // local col chunks; cb=3 all OOB
            __syncthreads();
            if (wn == cb) {
                #pragma unroll
                for (int ma = 0; ma < 4; ma++)
                    #pragma unroll
                    for (int na = 0; na < 4; na++)
                        #pragma unroll
                        for (int q = 0; q < 4; q++) {
                            int jc = na * 8 + 2 * t4 + (q & 1);
                            int il = wm * 64 + ma * 16 + g4 + 8 * (q >> 1);
                            S[jc * 132 + il] = acc[ma][na][q] * rnA[il] * rnBp[cb * 32 + jc];
                        }
            }
            __syncthreads();
            #pragma unroll
            for (int it = 0; it < 4; it++) {
                int jc = it * 8 + (tid >> 5);
                int gj = 128 + cb * 32 + jc;       // mirror row
                if (gj >= NN) continue;
                int i = (tid & 31) * 4;
                float4 v = *(float4*)&S[jc * 132 + i];
                if (v.x > 0.9f) rec_edge(b, gj, i + 0);
                if (v.y > 0.9f) rec_edge(b, gj, i + 1);
                if (v.z > 0.9f) rec_edge(b, gj, i + 2);
                if (v.w > 0.9f) rec_edge(b, gj, i + 3);
                *(float4*)&sim_out[((size_t)b * NN + gj) * NN + i] = v;
            }
        }
    }
}

// ---------------- kernel 5: grouping (edge-list driven) ----------------------
__global__ void __launch_bounds__(256, 1)
group_kernel(const float* __restrict__ sim_in_arg, float* out_gids) {
    int b = blockIdx.x, tid = threadIdx.x;
    const float* sim_in = sim_in_arg ? sim_in_arg : g_sim;
    __shared__ unsigned adj[NN][8];
    __shared__ float simp[NN];
    __shared__ int   sgid[NN];
    __shared__ float denom[NN];
    __shared__ int   cnt[NN];
    __shared__ int   off[NN + 1];
    __shared__ int   cur[NN];
    __shared__ unsigned assigned[8], reach[8], nxt[8];
    __shared__ int s_changed, s_ng, s_any;

    int ecnt = g_edge_cnt[b];

    for (int i = tid; i < NN; i += 256) {
        simp[i] = g_imp[b * NN + i];
        cnt[i] = 0;
        denom[i] = EPSF;
    }
    if (tid < 8) assigned[tid] = 0u;
    if (tid == 0) { s_ng = 0; s_any = 0; }
    __syncthreads();

    if (ecnt == 0) {
        for (int i = tid; i < NN; i += 256) sgid[i] = i;
        if (tid == 0) s_ng = NN;
        __syncthreads();
    } else {
        for (int i = tid; i < NN * 8; i += 256) (&adj[0][0])[i] = 0u;
        __syncthreads();
        if (ecnt <= EMAX) {
            for (int e = tid; e < ecnt; e += 256) {
                int pk = g_edges[b * EMAX + e];
                int i = pk >> 8, j = pk & 255;
                if (j < NN && (1.0f - simp[i]) > 0.5f) {
                    atomicOr(&adj[i][j >> 5], 1u << (j & 31));
                    s_any = 1;
                }
            }
        } else {
            const float* simb = sim_in + (size_t)b * NN * NN;
            for (int idx = tid; idx < NN * NN; idx += 256) {
                int i = idx / NN, j = idx - i * NN;
                float sv = simb[idx];
                if (sv > 0.9f && (1.0f - simp[i]) > 0.5f) {
                    atomicOr(&adj[i][j >> 5], 1u << (j & 31));
                    s_any = 1;
                }
            }
        }
        __syncthreads();

        if (s_any == 0) {
            for (int i = tid; i < NN; i += 256) sgid[i] = i;
            if (tid == 0) s_ng = NN;
            __syncthreads();
        } else {
            for (int r = 0; r < NN; r++) {
                if ((assigned[r >> 5] >> (r & 31)) & 1u) continue;
                if (tid < 8) reach[tid] = (tid == (r >> 5)) ? (1u << (r & 31)) : 0u;
                __syncthreads();
                while (true) {
                    if (tid < 8) nxt[tid] = 0u;
                    if (tid == 0) s_changed = 0;
                    __syncthreads();
                    for (int i = tid; i < NN; i += 256) {
                        if ((reach[i >> 5] >> (i & 31)) & 1u) {
                            #pragma unroll
                            for (int w = 0; w < 7; w++) {
                                unsigned v = adj[i][w];
                                if (v) atomicOr(&nxt[w], v);
                            }
                        }
                    }
                    __syncthreads();
                    if (tid < 8) {
                        unsigned nv = reach[tid] | (nxt[tid] & ~assigned[tid]);
                        if (nv != reach[tid]) s_changed = 1;
                        nxt[tid] = nv;
                    }
                    __syncthreads();
                    if (tid < 8) reach[tid] = nxt[tid];
                    __syncthreads();
                    if (!s_changed) break;
                }
                int gid = s_ng;
                for (int i = tid; i < NN; i += 256)
                    if ((reach[i >> 5] >> (i & 31)) & 1u) sgid[i] = gid;
                if (tid < 8) assigned[tid] |= reach[tid];
                __syncthreads();
                if (tid == 0) s_ng = gid + 1;
                __syncthreads();
            }
        }
    }

    for (int i = tid; i < NN; i += 256) atomicAdd(&denom[sgid[i]], simp[i]);
    __syncthreads();
    for (int i = tid; i < NN; i += 256) {
        g_w[b * NN + i]    = simp[i] / denom[sgid[i]];
        g_gids[b * NN + i] = sgid[i];
        if (out_gids) out_gids[b * NN + i] = (float)sgid[i];
        atomicAdd(&cnt[sgid[i]], 1);
    }
    __syncthreads();
    if (tid == 0) {
        off[0] = 0;
        for (int g = 0; g < NN; g++) off[g + 1] = off[g] + cnt[g];
    }
    __syncthreads();
    for (int g = tid; g < NN; g += 256) cur[g] = off[g];
    for (int g = tid; g < NN + 1; g += 256) g_goff[b * (NN + 1) + g] = off[g];
    __syncthreads();
    for (int i = tid; i < NN; i += 256) {
        int g = sgid[i];
        int pos = atomicAdd(&cur[g], 1);
        g_members[b * NN + pos] = i;
    }
}

// ---------------- kernel 6: merged tokens (CSR gather, float4) ----------------
__global__ void __launch_bounds__(192)
merge_kernel(const float* __restrict__ tok, float* __restrict__ out) {
    int b = blockIdx.y, g = blockIdx.x, tid = threadIdx.x;
    int o0 = g_goff[b * (NN + 1) + g];
    int o1 = g_goff[b * (NN + 1) + g + 1];
    float4 a = make_float4(0.f, 0.f, 0.f, 0.f);
    const float4* tokb = (const float4*)(tok + (size_t)b * NN * DD);
    for (int k = o0; k < o1; k++) {
        int i = g_members[b * NN + k];
        float wv = g_w[b * NN + i];
        float4 v = tokb[(size_t)i * (DD / 4) + tid];
        a.x += v.x * wv; a.y += v.y * wv; a.z += v.z * wv; a.w += v.w * wv;
    }
    ((float4*)out)[((size_t)b * NN + g) * (DD / 4) + tid] = a;
}

// ---------------- launch ------------------------------------------------------
extern "C" void kernel_launch(void* const* d_in, const int* in_sizes, int n_in,
                              void* d_out, int out_size) {
    const float* tokens = (const float*)d_in[0];
    const float* motion = (const float*)d_in[1];
    const float* sal    = (const float*)d_in[2];
    float* out = (float*)d_out;

    const long long SZ_M = (long long)BB * NN * DD;   // 19267584
    const long long SZ_S = (long long)BB * NN * NN;   //  4917248
    const long long SZ_I = (long long)BB * NN;        //    25088
    long long osz = (long long)out_size;

    float* out_sim  = (osz >= SZ_M + SZ_S)            ? out + SZ_M               : nullptr;
    float* out_imp  = (osz >= SZ_M + SZ_S + SZ_I)     ? out + SZ_M + SZ_S        : nullptr;
    float* out_gids = (osz >= SZ_M + SZ_S + 2 * SZ_I) ? out + SZ_M + SZ_S + SZ_I : nullptr;

    gmax2_kernel<<<2, 1024>>>(motion, sal, NTOK);
    imp_kernel<<<BB, 256>>>(motion, sal, out_imp);
    sim_kernel<<<dim3(3, BB), 256>>>(tokens, out_sim);
    group_kernel<<<BB, 256>>>(out_sim, out_gids);
    merge_kernel<<<dim3(NN, BB), 192>>>(tokens, out);
}